// round 8
// baseline (speedup 1.0000x reference)
#include <cuda_runtime.h>
#include <math.h>

#define Bb  4
#define Nn  2048
#define Ee  512
#define Hh  8
#define ATT_SCALE 0.125f   // 64^-0.5

// Scratch (device globals: allocation-guard safe)
__device__ float g_qkv[(size_t)Bb * Nn * 3 * Ee];   // ~50 MB
__device__ float g_ctx[(size_t)Bb * Nn * Ee];       // ~17 MB

// ---------------------------------------------------------------------------
// Helpers
// ---------------------------------------------------------------------------
__device__ __forceinline__ float f2tf(float x) {
    unsigned r;
    asm("cvt.rna.tf32.f32 %0, %1;" : "=r"(r) : "f"(x));
    return __uint_as_float(r);
}

__device__ __forceinline__ void mma_tf32(float c[4],
                                         float a0, float a1, float a2, float a3,
                                         float b0, float b1) {
    asm volatile(
        "mma.sync.aligned.m16n8k8.row.col.f32.tf32.tf32.f32 "
        "{%0,%1,%2,%3}, {%4,%5,%6,%7}, {%8,%9}, {%0,%1,%2,%3};"
        : "+f"(c[0]), "+f"(c[1]), "+f"(c[2]), "+f"(c[3])
        : "r"(__float_as_uint(a0)), "r"(__float_as_uint(a1)),
          "r"(__float_as_uint(a2)), "r"(__float_as_uint(a3)),
          "r"(__float_as_uint(b0)), "r"(__float_as_uint(b1)));
}

__device__ __forceinline__ void cp16(float* dst, const float* src) {
    unsigned sa = (unsigned)__cvta_generic_to_shared(dst);
    asm volatile("cp.async.cg.shared.global [%0], [%1], 16;" :: "r"(sa), "l"(src));
}
#define CP_COMMIT() asm volatile("cp.async.commit_group;")
#define CP_WAIT(n)  asm volatile("cp.async.wait_group %0;" :: "n"(n))

// ============================================================================
// TF32 GEMM (NT): C[M,N] = A[M,K] * B[N,K]^T + bias[N]
// 128x128x32 tiles, 2-stage cp.async pipeline, raw fp32 smem, f2tf at frag load.
// ============================================================================
#define GSTR 36
#define G_STAGE (2 * 128 * GSTR)            // floats per stage (As + Bs)
#define GEMM_SMEM_BYTES (2 * G_STAGE * 4)   // 73728

__global__ __launch_bounds__(256) void gemm_tf32(
    const float* __restrict__ A, const float* __restrict__ Bm,
    const float* __restrict__ bias, float* __restrict__ C,
    int M, int N, int K)
{
    extern __shared__ __align__(16) float gsm[];

    const int tid  = threadIdx.x;
    const int warp = tid >> 5, lane = tid & 31;
    const int grp  = lane >> 2, tig = lane & 3;
    const int bm = blockIdx.y * 128, bn = blockIdx.x * 128;
    const int wm = (warp & 3) * 32, wn = (warp >> 2) * 64;

    float acc[2][8][4];
    #pragma unroll
    for (int mt = 0; mt < 2; mt++)
        #pragma unroll
        for (int nt = 0; nt < 8; nt++)
            #pragma unroll
            for (int i = 0; i < 4; i++) acc[mt][nt][i] = 0.f;

    const int ldr = tid >> 3;        // 0..31
    const int ldc = (tid & 7) * 4;   // 0..28 step 4

    const float* Abase = A + (size_t)bm * K;
    const float* Bbase = Bm + (size_t)bn * K;

    // ---- prologue: stage 0
    {
        float* As = gsm;
        float* Bs = gsm + 128 * GSTR;
        #pragma unroll
        for (int i = 0; i < 4; i++) {
            int r = ldr + i * 32;
            cp16(&As[r * GSTR + ldc], Abase + (size_t)r * K + ldc);
            cp16(&Bs[r * GSTR + ldc], Bbase + (size_t)r * K + ldc);
        }
        CP_COMMIT();
    }

    const int NT = K >> 5;
    for (int t = 0; t < NT; t++) {
        const int cur = t & 1;
        if (t + 1 < NT) {
            float* As = gsm + (1 - cur) * G_STAGE;
            float* Bs = As + 128 * GSTR;
            int kt = (t + 1) << 5;
            #pragma unroll
            for (int i = 0; i < 4; i++) {
                int r = ldr + i * 32;
                cp16(&As[r * GSTR + ldc], Abase + (size_t)r * K + kt + ldc);
                cp16(&Bs[r * GSTR + ldc], Bbase + (size_t)r * K + kt + ldc);
            }
            CP_COMMIT();
            CP_WAIT(1);
        } else {
            CP_WAIT(0);
        }
        __syncthreads();

        const float* As = gsm + cur * G_STAGE;
        const float* Bs = As + 128 * GSTR;

        #pragma unroll
        for (int ks = 0; ks < 32; ks += 8) {
            float a[2][4];
            #pragma unroll
            for (int mt = 0; mt < 2; mt++) {
                a[mt][0] = f2tf(As[(wm + mt * 16 + grp) * GSTR + ks + tig]);
                a[mt][1] = f2tf(As[(wm + mt * 16 + grp + 8) * GSTR + ks + tig]);
                a[mt][2] = f2tf(As[(wm + mt * 16 + grp) * GSTR + ks + tig + 4]);
                a[mt][3] = f2tf(As[(wm + mt * 16 + grp + 8) * GSTR + ks + tig + 4]);
            }
            #pragma unroll
            for (int nt = 0; nt < 8; nt++) {
                float b0 = f2tf(Bs[(wn + nt * 8 + grp) * GSTR + ks + tig]);
                float b1 = f2tf(Bs[(wn + nt * 8 + grp) * GSTR + ks + tig + 4]);
                mma_tf32(acc[0][nt], a[0][0], a[0][1], a[0][2], a[0][3], b0, b1);
                mma_tf32(acc[1][nt], a[1][0], a[1][1], a[1][2], a[1][3], b0, b1);
            }
        }
        __syncthreads();   // reads of 'cur' done before iter t+2 overwrites it
    }

    #pragma unroll
    for (int nt = 0; nt < 8; nt++) {
        int col = bn + wn + nt * 8 + tig * 2;
        float2 bv = *(const float2*)(bias + col);
        #pragma unroll
        for (int mt = 0; mt < 2; mt++) {
            int r0 = bm + wm + mt * 16 + grp;
            *(float2*)(C + (size_t)r0 * N + col) =
                make_float2(acc[mt][nt][0] + bv.x, acc[mt][nt][1] + bv.y);
            *(float2*)(C + (size_t)(r0 + 8) * N + col) =
                make_float2(acc[mt][nt][2] + bv.x, acc[mt][nt][3] + bv.y);
        }
    }
}

// ============================================================================
// Flash attention v3: 128 queries/CTA, 8 warps each m16 x n64.
// 2-stage cp.async K/V pipeline; S/softmax in registers; Q in registers.
// smem: 2 x (Ks[64][68] + Vs[64][72]) + Ps[128][68]  = ~104 KB.
// ============================================================================
#define KSTR 68
#define VSTR 72
#define PSTR 68
#define KV_STAGE (64 * KSTR + 64 * VSTR)    // floats per stage
#define PS_OFF   (2 * KV_STAGE)
#define ATT_SMEM_FLOATS (2 * KV_STAGE + 128 * PSTR)
#define ATT_SMEM_BYTES  (ATT_SMEM_FLOATS * 4)

__global__ __launch_bounds__(256, 2) void attn_tf32()
{
    extern __shared__ __align__(16) float sm[];
    float* Ps = sm + PS_OFF;              // [128][68], also Q staging

    const int tid  = threadIdx.x;
    const int warp = tid >> 5, lane = tid & 31;
    const int grp  = lane >> 2, tig = lane & 3;
    const int wm = warp * 16;             // q-rows [wm, wm+16)

    const int bh = blockIdx.y;
    const int b = bh >> 3, h = bh & 7;
    const int q0 = blockIdx.x * 128;

    const float* qbase = g_qkv + (size_t)b * Nn * 1536 + h * 64;
    const float* kbase = qbase + 512;
    const float* vbase = qbase + 1024;

    const int lrow2 = tid >> 2;          // 0..63
    const int lseg2 = (tid & 3) * 16;    // 0,16,32,48

    // ---- prologue: kick off K/V tile 0 into stage 0 (overlaps Q staging)
    {
        float* Ks = sm;
        float* Vs = sm + 64 * KSTR;
        const float* kp = kbase + (size_t)lrow2 * 1536 + lseg2;
        const float* vp = vbase + (size_t)lrow2 * 1536 + lseg2;
        #pragma unroll
        for (int u = 0; u < 4; u++) {
            cp16(&Ks[lrow2 * KSTR + lseg2 + u * 4], kp + u * 4);
            cp16(&Vs[lrow2 * VSTR + lseg2 + u * 4], vp + u * 4);
        }
        CP_COMMIT();
    }

    // ---- Stage Q tile (128x64, scaled, tf32) into Ps, lift to registers
    {
        const int lrow = tid >> 1;          // 0..127
        const int lseg = (tid & 1) * 32;    // 0 or 32
        const float* qp = qbase + (size_t)(q0 + lrow) * 1536 + lseg;
        #pragma unroll
        for (int u = 0; u < 8; u++) {
            float4 v = *(const float4*)(qp + u * 4);
            *(float4*)&Ps[lrow * PSTR + lseg + u * 4] = make_float4(
                f2tf(v.x * ATT_SCALE), f2tf(v.y * ATT_SCALE),
                f2tf(v.z * ATT_SCALE), f2tf(v.w * ATT_SCALE));
        }
    }
    __syncthreads();

    float qf[8][4];
    #pragma unroll
    for (int ks = 0; ks < 8; ks++) {
        qf[ks][0] = Ps[(wm + grp) * PSTR + ks * 8 + tig];
        qf[ks][1] = Ps[(wm + grp + 8) * PSTR + ks * 8 + tig];
        qf[ks][2] = Ps[(wm + grp) * PSTR + ks * 8 + tig + 4];
        qf[ks][3] = Ps[(wm + grp + 8) * PSTR + ks * 8 + tig + 4];
    }

    float o[8][4];
    #pragma unroll
    for (int nt = 0; nt < 8; nt++)
        #pragma unroll
        for (int i = 0; i < 4; i++) o[nt][i] = 0.f;

    float m_a = -1e30f, m_b = -1e30f, l_a = 0.f, l_b = 0.f;

    const int NTILE = Nn / 64;   // 32
    for (int t = 0; t < NTILE; t++) {
        const int cur = t & 1;

        // ---- prefetch next K/V tile into the other stage
        if (t + 1 < NTILE) {
            float* Ks = sm + (1 - cur) * KV_STAGE;
            float* Vs = Ks + 64 * KSTR;
            int kt = (t + 1) * 64;
            const float* kp = kbase + (size_t)(kt + lrow2) * 1536 + lseg2;
            const float* vp = vbase + (size_t)(kt + lrow2) * 1536 + lseg2;
            #pragma unroll
            for (int u = 0; u < 4; u++) {
                cp16(&Ks[lrow2 * KSTR + lseg2 + u * 4], kp + u * 4);
                cp16(&Vs[lrow2 * VSTR + lseg2 + u * 4], vp + u * 4);
            }
            CP_COMMIT();
            CP_WAIT(1);
        } else {
            CP_WAIT(0);
        }
        __syncthreads();   // stage 'cur' complete for all threads
                           // (also: iter 0 guards Ps Q-frag reads vs P writes)

        const float* Ks = sm + cur * KV_STAGE;
        const float* Vs = Ks + 64 * KSTR;

        // ---- S = Q K^T  (warp: m16 x n64, k=64), accumulators in registers
        float sc[8][4];
        #pragma unroll
        for (int nt = 0; nt < 8; nt++)
            #pragma unroll
            for (int i = 0; i < 4; i++) sc[nt][i] = 0.f;

        #pragma unroll
        for (int ks = 0; ks < 8; ks++) {
            #pragma unroll
            for (int nt = 0; nt < 8; nt++) {
                float b0 = f2tf(Ks[(nt * 8 + grp) * KSTR + ks * 8 + tig]);
                float b1 = f2tf(Ks[(nt * 8 + grp) * KSTR + ks * 8 + tig + 4]);
                mma_tf32(sc[nt], qf[ks][0], qf[ks][1], qf[ks][2], qf[ks][3], b0, b1);
            }
        }

        // ---- Online softmax in registers
        {
            float mx_a = -1e30f, mx_b = -1e30f;
            #pragma unroll
            for (int nt = 0; nt < 8; nt++) {
                mx_a = fmaxf(mx_a, fmaxf(sc[nt][0], sc[nt][1]));
                mx_b = fmaxf(mx_b, fmaxf(sc[nt][2], sc[nt][3]));
            }
            mx_a = fmaxf(mx_a, __shfl_xor_sync(0xffffffffu, mx_a, 1));
            mx_a = fmaxf(mx_a, __shfl_xor_sync(0xffffffffu, mx_a, 2));
            mx_b = fmaxf(mx_b, __shfl_xor_sync(0xffffffffu, mx_b, 1));
            mx_b = fmaxf(mx_b, __shfl_xor_sync(0xffffffffu, mx_b, 2));

            float mn_a = fmaxf(m_a, mx_a);
            float mn_b = fmaxf(m_b, mx_b);

            float sum_a = 0.f, sum_b = 0.f;
            #pragma unroll
            for (int nt = 0; nt < 8; nt++) {
                sc[nt][0] = __expf(sc[nt][0] - mn_a);
                sc[nt][1] = __expf(sc[nt][1] - mn_a);
                sc[nt][2] = __expf(sc[nt][2] - mn_b);
                sc[nt][3] = __expf(sc[nt][3] - mn_b);
                sum_a += sc[nt][0] + sc[nt][1];
                sum_b += sc[nt][2] + sc[nt][3];
            }
            sum_a += __shfl_xor_sync(0xffffffffu, sum_a, 1);
            sum_a += __shfl_xor_sync(0xffffffffu, sum_a, 2);
            sum_b += __shfl_xor_sync(0xffffffffu, sum_b, 1);
            sum_b += __shfl_xor_sync(0xffffffffu, sum_b, 2);

            float alpha_a = __expf(m_a - mn_a);
            float alpha_b = __expf(m_b - mn_b);
            l_a = l_a * alpha_a + sum_a;
            l_b = l_b * alpha_b + sum_b;
            m_a = mn_a;
            m_b = mn_b;

            #pragma unroll
            for (int nt = 0; nt < 8; nt++) {
                o[nt][0] *= alpha_a; o[nt][1] *= alpha_a;
                o[nt][2] *= alpha_b; o[nt][3] *= alpha_b;
            }
        }

        // ---- Store P (tf32) to this warp's own rows of Ps
        #pragma unroll
        for (int nt = 0; nt < 8; nt++) {
            *(float2*)&Ps[(wm + grp) * PSTR + nt * 8 + tig * 2] =
                make_float2(f2tf(sc[nt][0]), f2tf(sc[nt][1]));
            *(float2*)&Ps[(wm + grp + 8) * PSTR + nt * 8 + tig * 2] =
                make_float2(f2tf(sc[nt][2]), f2tf(sc[nt][3]));
        }
        __syncwarp();   // warp reads only its own 16 rows

        // ---- O += P @ V  (warp: m16 x n64 over d, k=64 keys)
        #pragma unroll
        for (int ks = 0; ks < 8; ks++) {
            float a0 = Ps[(wm + grp) * PSTR + ks * 8 + tig];
            float a1 = Ps[(wm + grp + 8) * PSTR + ks * 8 + tig];
            float a2 = Ps[(wm + grp) * PSTR + ks * 8 + tig + 4];
            float a3 = Ps[(wm + grp + 8) * PSTR + ks * 8 + tig + 4];
            #pragma unroll
            for (int nt = 0; nt < 8; nt++) {
                float b0 = f2tf(Vs[(ks * 8 + tig) * VSTR + nt * 8 + grp]);
                float b1 = f2tf(Vs[(ks * 8 + tig + 4) * VSTR + nt * 8 + grp]);
                mma_tf32(o[nt], a0, a1, a2, a3, b0, b1);
            }
        }
        __syncthreads();   // reads of stage 'cur' done before iter t+2 refills it
    }

    // ---- Normalize and write out
    float inv_a = 1.0f / l_a;
    float inv_b = 1.0f / l_b;
    #pragma unroll
    for (int nt = 0; nt < 8; nt++) {
        int col = h * 64 + nt * 8 + tig * 2;
        float* c0 = g_ctx + ((size_t)b * Nn + q0 + wm + grp) * Ee + col;
        *(float2*)c0 = make_float2(o[nt][0] * inv_a, o[nt][1] * inv_a);
        float* c1 = g_ctx + ((size_t)b * Nn + q0 + wm + grp + 8) * Ee + col;
        *(float2*)c1 = make_float2(o[nt][2] * inv_b, o[nt][3] * inv_b);
    }
}

// ============================================================================
// Host launch
// ============================================================================
extern "C" void kernel_launch(void* const* d_in, const int* in_sizes, int n_in,
                              void* d_out, int out_size)
{
    const float* x     = (const float*)d_in[0];
    const float* w_qkv = (const float*)d_in[1];
    const float* b_qkv = (const float*)d_in[2];
    const float* w_out = (const float*)d_in[3];
    const float* b_out = (const float*)d_in[4];
    float* out = (float*)d_out;

    void* qkv_ptr = nullptr;
    void* ctx_ptr = nullptr;
    cudaGetSymbolAddress(&qkv_ptr, g_qkv);
    cudaGetSymbolAddress(&ctx_ptr, g_ctx);
    float* qkv = (float*)qkv_ptr;
    float* ctx = (float*)ctx_ptr;

    cudaFuncSetAttribute(gemm_tf32, cudaFuncAttributeMaxDynamicSharedMemorySize,
                         GEMM_SMEM_BYTES);
    cudaFuncSetAttribute(attn_tf32, cudaFuncAttributeMaxDynamicSharedMemorySize,
                         ATT_SMEM_BYTES);

    const int M = Bb * Nn;  // 8192

    // 1) QKV projection
    gemm_tf32<<<dim3(3 * Ee / 128, M / 128), 256, GEMM_SMEM_BYTES>>>(
        x, w_qkv, b_qkv, qkv, M, 3 * Ee, Ee);

    // 2) Attention: 128-query tiles
    attn_tf32<<<dim3(Nn / 128, Bb * Hh), 256, ATT_SMEM_BYTES>>>();

    // 3) Output projection
    gemm_tf32<<<dim3(Ee / 128, M / 128), 256, GEMM_SMEM_BYTES>>>(
        ctx, w_out, b_out, out, M, Ee, Ee);
}